// round 5
// baseline (speedup 1.0000x reference)
#include <cuda_runtime.h>

#define B_TOK 8192
#define D_DIM 2048
#define F_DIM 16384
#define TOPK  64
#define EPS_WIN 4e-4f
#define MAXCAND 128

// ---------------- scratch (static device globals; no allocation) ----------------
__device__ __align__(256) float g_pre[(size_t)B_TOK * F_DIM];   // 512 MB
__device__ __align__(256) float g_WdT[(size_t)F_DIM * D_DIM];   // 128 MB
__device__ __align__(256) float g_cbias[F_DIM];
__device__ __align__(256) float g_vals[B_TOK * TOPK];
__device__ __align__(256) int   g_idx[B_TOK * TOPK];

// monotone float<->uint mapping for radix select
__device__ __forceinline__ unsigned f2u(float f) {
    unsigned v = __float_as_uint(f);
    return (v & 0x80000000u) ? ~v : (v | 0x80000000u);
}
__device__ __forceinline__ float u2f(unsigned v) {
    unsigned o = (v & 0x80000000u) ? (v ^ 0x80000000u) : ~v;
    return __uint_as_float(o);
}

// ---------------- cbias[f] = b_enc[f] - dot(b_dec, W_enc[f,:]) ----------------
__global__ void cbias_kernel(const float* __restrict__ W_enc,
                             const float* __restrict__ b_enc,
                             const float* __restrict__ b_dec) {
    int wid  = threadIdx.x >> 5;
    int lane = threadIdx.x & 31;
    int f    = blockIdx.x * 8 + wid;
    const float* w = W_enc + (size_t)f * D_DIM;
    float s = 0.f;
    for (int d = lane; d < D_DIM; d += 32) s += b_dec[d] * w[d];
#pragma unroll
    for (int o = 16; o > 0; o >>= 1) s += __shfl_xor_sync(0xFFFFFFFFu, s, o);
    if (lane == 0) g_cbias[f] = b_enc[f] - s;
}

// ---------------- W_decT[f][d] = W_dec[d][f] ----------------
__global__ void transpose_kernel(const float* __restrict__ W_dec) {
    __shared__ float t[32][33];
    int fb = blockIdx.x * 32, db = blockIdx.y * 32;
    int tx = threadIdx.x, ty = threadIdx.y;  // 32 x 8
#pragma unroll
    for (int i = 0; i < 32; i += 8)
        t[ty + i][tx] = W_dec[(size_t)(db + ty + i) * F_DIM + fb + tx];
    __syncthreads();
#pragma unroll
    for (int i = 0; i < 32; i += 8)
        g_WdT[(size_t)(fb + ty + i) * D_DIM + db + tx] = t[tx][ty + i];
}

// ---------------- encode GEMM: g_pre = x @ W_enc^T + cbias ----------------
// 128x128 tile, BK=16, 256 threads, 8x8 per thread, fp32 FFMA.
__global__ __launch_bounds__(256) void gemm_kernel(const float* __restrict__ A,
                                                   const float* __restrict__ W) {
    __shared__ float As[16][132];
    __shared__ float Bs[16][132];
    const int tid = threadIdx.x;
    const int tx = tid & 15;
    const int ty = tid >> 4;
    const size_t aBase = (size_t)blockIdx.y * 128 * D_DIM;
    const size_t bBase = (size_t)blockIdx.x * 128 * D_DIM;

    float acc[8][8];
#pragma unroll
    for (int i = 0; i < 8; i++)
#pragma unroll
        for (int j = 0; j < 8; j++) acc[i][j] = 0.f;

    const int r0 = tid >> 2;         // 0..63
    const int c0 = (tid & 3) * 4;    // 0,4,8,12

    for (int k0 = 0; k0 < D_DIM; k0 += 16) {
#pragma unroll
        for (int h = 0; h < 2; h++) {
            int row = r0 + h * 64;
            float4 va = *(const float4*)(A + aBase + (size_t)row * D_DIM + k0 + c0);
            As[c0 + 0][row] = va.x; As[c0 + 1][row] = va.y;
            As[c0 + 2][row] = va.z; As[c0 + 3][row] = va.w;
            float4 vb = *(const float4*)(W + bBase + (size_t)row * D_DIM + k0 + c0);
            Bs[c0 + 0][row] = vb.x; Bs[c0 + 1][row] = vb.y;
            Bs[c0 + 2][row] = vb.z; Bs[c0 + 3][row] = vb.w;
        }
        __syncthreads();
#pragma unroll
        for (int k = 0; k < 16; k++) {
            float ra[8], rb[8];
            *(float4*)(ra)     = *(const float4*)&As[k][ty * 8];
            *(float4*)(ra + 4) = *(const float4*)&As[k][ty * 8 + 4];
            *(float4*)(rb)     = *(const float4*)&Bs[k][tx * 8];
            *(float4*)(rb + 4) = *(const float4*)&Bs[k][tx * 8 + 4];
#pragma unroll
            for (int i = 0; i < 8; i++)
#pragma unroll
                for (int j = 0; j < 8; j++)
                    acc[i][j] = fmaf(ra[i], rb[j], acc[i][j]);
        }
        __syncthreads();
    }
    const int m0 = blockIdx.y * 128 + ty * 8;
    const int n0 = blockIdx.x * 128 + tx * 8;
    float cb[8];
#pragma unroll
    for (int j = 0; j < 8; j++) cb[j] = g_cbias[n0 + j];
#pragma unroll
    for (int i = 0; i < 8; i++) {
        float4 o0 = make_float4(acc[i][0] + cb[0], acc[i][1] + cb[1],
                                acc[i][2] + cb[2], acc[i][3] + cb[3]);
        float4 o1 = make_float4(acc[i][4] + cb[4], acc[i][5] + cb[5],
                                acc[i][6] + cb[6], acc[i][7] + cb[7]);
        *(float4*)&g_pre[(size_t)(m0 + i) * F_DIM + n0]     = o0;
        *(float4*)&g_pre[(size_t)(m0 + i) * F_DIM + n0 + 4] = o1;
    }
}

// ---------------- per-row top-64: radix select + fp64 boundary arbitration ----------------
__global__ __launch_bounds__(256) void topk_kernel(const float* __restrict__ x,
                                                   const float* __restrict__ W_enc,
                                                   const float* __restrict__ b_enc,
                                                   const float* __restrict__ b_dec) {
    extern __shared__ unsigned u[];            // 16384 keys (64KB)
    __shared__ unsigned whist[8][16];
    __shared__ unsigned tot[16];
    __shared__ unsigned sel[2];
    __shared__ unsigned gcnt[8];
    __shared__ unsigned gbase;
    __shared__ int s_ncand;
    __shared__ int      cand_idx[MAXCAND];
    __shared__ unsigned cand_key[MAXCAND];
    __shared__ double   cand_val[MAXCAND];
    __shared__ double   red[8];
    const int tid = threadIdx.x, wid = tid >> 5, lane = tid & 31;
    const int row = blockIdx.x;
    const float* __restrict__ src = g_pre + (size_t)row * F_DIM;

#pragma unroll
    for (int j = 0; j < 64; j++)
        u[tid + j * 256] = f2u(src[tid + j * 256]);

    // ---- radix select: find key of the 64th largest value ----
    unsigned prefix = 0;
    int need = TOPK;
    for (int shift = 28; shift >= 0; shift -= 4) {
        if (tid < 128) ((unsigned*)whist)[tid] = 0;
        __syncthreads();
        const unsigned maskhi = (shift == 28) ? 0u : (0xFFFFFFFFu << (shift + 4));
        for (int j = 0; j < 64; j++) {
            unsigned v = u[tid + j * 256];
            if ((v & maskhi) == prefix)
                atomicAdd(&whist[wid][(v >> shift) & 15u], 1u);
        }
        __syncthreads();
        if (tid < 16) {
            unsigned s = 0;
#pragma unroll
            for (int w = 0; w < 8; w++) s += whist[w][tid];
            tot[tid] = s;
        }
        __syncthreads();
        if (tid == 0) {
            int nd = need, b = 15;
            for (; b > 0; b--) {
                if ((int)tot[b] >= nd) break;
                nd -= (int)tot[b];
            }
            sel[0] = (unsigned)b;
            sel[1] = (unsigned)nd;
        }
        __syncthreads();
        prefix |= sel[0] << shift;
        need = (int)sel[1];
        __syncthreads();
    }

    // ---- ambiguity window around v64 ----
    const float vC = u2f(prefix);
    const unsigned keyHi = f2u(vC + EPS_WIN);
    const unsigned keyLo = f2u(vC - EPS_WIN);

    if (tid == 0) { gbase = 0; s_ncand = 0; }
    __syncthreads();

    float* vout = g_vals + (size_t)row * TOPK;
    int*   iout = g_idx + (size_t)row * TOPK;
    const unsigned lt = (1u << lane) - 1u;

    // scatter certain-in (key > keyHi) in ascending index order; collect candidates
    for (int base = 0; base < F_DIM; base += 256) {
        unsigned v = u[base + tid];
        bool fgt   = (v > keyHi);
        bool fcand = (v >= keyLo) && (v <= keyHi);
        unsigned balg = __ballot_sync(0xFFFFFFFFu, fgt);
        if (lane == 0) gcnt[wid] = __popc(balg);
        __syncthreads();
        if (tid == 0) {
            unsigned rg = gbase;
#pragma unroll
            for (int w = 0; w < 8; w++) {
                unsigned cg = gcnt[w]; gcnt[w] = rg; rg += cg;
            }
            gbase = rg;
        }
        __syncthreads();
        if (fgt) {
            int slot = (int)gcnt[wid] + __popc(balg & lt);
            iout[slot] = base + tid;
            vout[slot] = u2f(v);
        }
        if (fcand) {
            int p = atomicAdd(&s_ncand, 1);
            if (p < MAXCAND) { cand_idx[p] = base + tid; cand_key[p] = v; }
        }
        __syncthreads();
    }

    const int ncert = (int)gbase;
    const int slots = TOPK - ncert;
    int ncand = s_ncand;
    if (ncand > MAXCAND) ncand = MAXCAND;

    // contested boundary: recompute candidate dots in fp64 (block-cooperative)
    if (ncand > slots) {
        const float* __restrict__ xr = x + (size_t)row * D_DIM;
        for (int c = 0; c < ncand; c++) {
            const float* __restrict__ w = W_enc + (size_t)cand_idx[c] * D_DIM;
            double p = 0.0;
            for (int d = tid; d < D_DIM; d += 256)
                p += (double)(xr[d] - b_dec[d]) * (double)w[d];
#pragma unroll
            for (int o = 16; o > 0; o >>= 1) p += __shfl_xor_sync(0xFFFFFFFFu, p, o);
            if (lane == 0) red[wid] = p;
            __syncthreads();
            if (tid == 0) {
                double s = 0.0;
#pragma unroll
                for (int w8 = 0; w8 < 8; w8++) s += red[w8];
                cand_val[c] = s + (double)b_enc[cand_idx[c]];
            }
            __syncthreads();
        }
    }

    // thread 0: deterministic selection + placement of the remaining slots
    if (tid == 0) {
        bool used[MAXCAND];
        for (int c = 0; c < ncand; c++) used[c] = false;
        if (ncand == slots) {
            // all candidates selected: place in ascending feature-index order
            for (int s = 0; s < slots; s++) {
                int best = -1;
                for (int c = 0; c < ncand; c++)
                    if (!used[c] && (best < 0 || cand_idx[c] < cand_idx[best])) best = c;
                used[best] = true;
                iout[ncert + s] = cand_idx[best];
                vout[ncert + s] = u2f(cand_key[best]);
            }
        } else {
            // refined selection: fp64 value desc; equal fp32 keys -> lowest index
            for (int s = 0; s < slots; s++) {
                int best = -1;
                for (int c = 0; c < ncand; c++) {
                    if (used[c]) continue;
                    if (best < 0) { best = c; continue; }
                    bool b;
                    if (cand_key[c] == cand_key[best])      b = cand_idx[c] < cand_idx[best];
                    else if (cand_val[c] != cand_val[best]) b = cand_val[c] > cand_val[best];
                    else                                    b = cand_key[c] > cand_key[best];
                    if (b) best = c;
                }
                used[best] = true;
                iout[ncert + s] = cand_idx[best];
                vout[ncert + s] = u2f(cand_key[best]);
            }
        }
    }
}

// ---------------- sparse decode: out[b,:] = b_dec + sum_k val*W_decT[idx,:] ----------------
__global__ __launch_bounds__(256) void decode_kernel(const float* __restrict__ b_dec,
                                                     float* __restrict__ out) {
    __shared__ float sv[TOPK];
    __shared__ int   si[TOPK];
    const int row = blockIdx.x, tid = threadIdx.x;
    if (tid < TOPK) {
        sv[tid] = g_vals[(size_t)row * TOPK + tid];
        si[tid] = g_idx[(size_t)row * TOPK + tid];
    }
    __syncthreads();
    const float4* bd = (const float4*)b_dec;
    float4 a0 = bd[tid], a1 = bd[tid + 256];
#pragma unroll 4
    for (int k = 0; k < TOPK; k++) {
        const float v = sv[k];
        const float4* wr = (const float4*)(g_WdT + (size_t)si[k] * D_DIM);
        float4 w0 = wr[tid], w1 = wr[tid + 256];
        a0.x = fmaf(v, w0.x, a0.x); a0.y = fmaf(v, w0.y, a0.y);
        a0.z = fmaf(v, w0.z, a0.z); a0.w = fmaf(v, w0.w, a0.w);
        a1.x = fmaf(v, w1.x, a1.x); a1.y = fmaf(v, w1.y, a1.y);
        a1.z = fmaf(v, w1.z, a1.z); a1.w = fmaf(v, w1.w, a1.w);
    }
    float4* o = (float4*)out;
    o[(size_t)row * 512 + tid]       = a0;
    o[(size_t)row * 512 + 256 + tid] = a1;
}

// ---------------- launch ----------------
extern "C" void kernel_launch(void* const* d_in, const int* in_sizes, int n_in,
                              void* d_out, int out_size) {
    const float* x     = (const float*)d_in[0];
    const float* W_enc = (const float*)d_in[1];
    const float* b_enc = (const float*)d_in[2];
    const float* W_dec = (const float*)d_in[3];
    const float* b_dec = (const float*)d_in[4];
    float* out = (float*)d_out;

    cbias_kernel<<<F_DIM / 8, 256>>>(W_enc, b_enc, b_dec);
    transpose_kernel<<<dim3(F_DIM / 32, D_DIM / 32), dim3(32, 8)>>>(W_dec);
    gemm_kernel<<<dim3(F_DIM / 128, B_TOK / 128), 256>>>(x, W_enc);
    cudaFuncSetAttribute(topk_kernel, cudaFuncAttributeMaxDynamicSharedMemorySize, 65536);
    topk_kernel<<<B_TOK, 256, 65536>>>(x, W_enc, b_enc, b_dec);
    decode_kernel<<<B_TOK, 256>>>(b_dec, out);
}

// round 10
// speedup vs baseline: 1.9971x; 1.9971x over previous
#include <cuda_runtime.h>
#include <cuda_bf16.h>
#include <cstdint>

#define B_TOK 8192
#define D_DIM 2048
#define F_DIM 16384
#define TOPK  64
#define EPS_WIN 6e-4f
#define MAXCAND 128

// ---- GEMM tiling ----
#define TM 128
#define TN 128
#define KT 32
#define NCHUNK (D_DIM / KT)      // 64
#define NT_M (B_TOK / TM)        // 64
#define NT_N (F_DIM / TN)        // 128
// per-stage smem: A0(8K) A1(8K) B0(8K) B1(8K) = 32KB; 2 stages = 64KB
#define STAGE_BYTES 32768
#define OFF_A1 8192
#define OFF_B0 16384
#define OFF_B1 24576
#define SMEM_GEMM (2 * STAGE_BYTES)

// ---------------- scratch (static device globals; no allocation) ----------------
__device__ __align__(256) float g_pre[(size_t)B_TOK * F_DIM];   // 512 MB
__device__ __align__(256) float g_WdT[(size_t)F_DIM * D_DIM];   // 128 MB
__device__ __align__(256) float g_cbias[F_DIM];
__device__ __align__(256) float g_vals[B_TOK * TOPK];
__device__ __align__(256) int   g_idx[B_TOK * TOPK];

// ---------------- helpers ----------------
__device__ __forceinline__ uint32_t smem_u32(const void* p) {
    uint32_t a;
    asm("{ .reg .u64 t; cvta.to.shared.u64 t, %1; cvt.u32.u64 %0, t; }" : "=r"(a) : "l"(p));
    return a;
}
#define LDSM4(r, a) \
    asm volatile("ldmatrix.sync.aligned.m8n8.x4.shared.b16 {%0,%1,%2,%3}, [%4];" \
        : "=r"((r)[0]), "=r"((r)[1]), "=r"((r)[2]), "=r"((r)[3]) : "r"(a))
#define MMA16816(c, a, b) \
    asm volatile("mma.sync.aligned.m16n8k16.row.col.f32.bf16.bf16.f32 " \
        "{%0,%1,%2,%3}, {%4,%5,%6,%7}, {%8,%9}, {%0,%1,%2,%3};" \
        : "+f"((c)[0]), "+f"((c)[1]), "+f"((c)[2]), "+f"((c)[3]) \
        : "r"((a)[0]), "r"((a)[1]), "r"((a)[2]), "r"((a)[3]), "r"((b)[0]), "r"((b)[1]))

__device__ __forceinline__ uint32_t bfpack(__nv_bfloat16 a, __nv_bfloat16 b) {
    return (uint32_t)__bfloat16_as_ushort(a) | ((uint32_t)__bfloat16_as_ushort(b) << 16);
}
// split float4 into bf16 hi/lo pairs; store 8B each to smem
__device__ __forceinline__ void split_store(char* p_hi, char* p_lo, float4 v) {
    __nv_bfloat16 hx = __float2bfloat16_rn(v.x), hy = __float2bfloat16_rn(v.y);
    __nv_bfloat16 hz = __float2bfloat16_rn(v.z), hw = __float2bfloat16_rn(v.w);
    uint2 h = make_uint2(bfpack(hx, hy), bfpack(hz, hw));
    __nv_bfloat16 lx = __float2bfloat16_rn(v.x - __bfloat162float(hx));
    __nv_bfloat16 ly = __float2bfloat16_rn(v.y - __bfloat162float(hy));
    __nv_bfloat16 lz = __float2bfloat16_rn(v.z - __bfloat162float(hz));
    __nv_bfloat16 lw = __float2bfloat16_rn(v.w - __bfloat162float(hw));
    uint2 l = make_uint2(bfpack(lx, ly), bfpack(lz, lw));
    *(uint2*)p_hi = h;
    *(uint2*)p_lo = l;
}

// monotone float<->uint mapping for radix select
__device__ __forceinline__ unsigned f2u(float f) {
    unsigned v = __float_as_uint(f);
    return (v & 0x80000000u) ? ~v : (v | 0x80000000u);
}
__device__ __forceinline__ float u2f(unsigned v) {
    unsigned o = (v & 0x80000000u) ? (v ^ 0x80000000u) : ~v;
    return __uint_as_float(o);
}

// ---------------- cbias[f] = b_enc[f] - dot(b_dec, W_enc[f,:]) ----------------
__global__ void cbias_kernel(const float* __restrict__ W_enc,
                             const float* __restrict__ b_enc,
                             const float* __restrict__ b_dec) {
    int wid  = threadIdx.x >> 5;
    int lane = threadIdx.x & 31;
    int f    = blockIdx.x * 8 + wid;
    const float* w = W_enc + (size_t)f * D_DIM;
    float s = 0.f;
    for (int d = lane; d < D_DIM; d += 32) s += b_dec[d] * w[d];
#pragma unroll
    for (int o = 16; o > 0; o >>= 1) s += __shfl_xor_sync(0xFFFFFFFFu, s, o);
    if (lane == 0) g_cbias[f] = b_enc[f] - s;
}

// ---------------- W_decT[f][d] = W_dec[d][f] ----------------
__global__ void transpose_kernel(const float* __restrict__ W_dec) {
    __shared__ float t[32][33];
    int fb = blockIdx.x * 32, db = blockIdx.y * 32;
    int tx = threadIdx.x, ty = threadIdx.y;  // 32 x 8
#pragma unroll
    for (int i = 0; i < 32; i += 8)
        t[ty + i][tx] = W_dec[(size_t)(db + ty + i) * F_DIM + fb + tx];
    __syncthreads();
#pragma unroll
    for (int i = 0; i < 32; i += 8)
        g_WdT[(size_t)(fb + ty + i) * D_DIM + db + tx] = t[tx][ty + i];
}

// ---------------- encode GEMM: mma.sync bf16 3-product split, fp32 accum ----------------
// CTA tile 128x128, K chunk 32, 8 warps in 4(M) x 2(N), warp tile 32x64.
__global__ __launch_bounds__(256, 1) void gemm_mma_kernel(const float* __restrict__ A,
                                                          const float* __restrict__ W) {
    extern __shared__ char smem[];
    const uint32_t sb = smem_u32(smem);
    const int tid = threadIdx.x, lane = tid & 31, wid = tid >> 5;
    const int wm = wid & 3, wn = wid >> 2;

    // grid swizzle: groups of 8 N-tiles over all 64 M-tiles
    const int group = blockIdx.x >> 9;
    const int rr    = blockIdx.x & 511;
    const int nt    = group * 8 + (rr & 7);
    const int mt    = rr >> 3;
    const int m0 = mt * TM, n0 = nt * TN;

    // loader mapping: 8 threads per row (float4 each), 32 rows per pass, 4 passes
    const int lrow = tid >> 3;        // 0..31
    const int lc4  = tid & 7;         // float4 index; k = lc4*4
    const int lchunk = lc4 >> 1, lhalf = lc4 & 1;

    float4 la[4], lb[4];

#define LOADC(c) do { const int k0 = (c) * KT;                                           \
    _Pragma("unroll") for (int p = 0; p < 4; p++) {                                      \
        la[p] = *(const float4*)(A + (size_t)(m0 + lrow + 32*p) * D_DIM + k0 + lc4*4);   \
        lb[p] = *(const float4*)(W + (size_t)(n0 + lrow + 32*p) * D_DIM + k0 + lc4*4);   \
    } } while (0)

#define STOREC(st) do { char* sg = smem + (st) * STAGE_BYTES;                            \
    _Pragma("unroll") for (int p = 0; p < 4; p++) {                                      \
        int row = lrow + 32*p;                                                           \
        uint32_t off = (uint32_t)row*64u + (uint32_t)((lchunk ^ ((row>>1)&3))*16 + lhalf*8); \
        split_store(sg + off,          sg + OFF_A1 + off, la[p]);                        \
        split_store(sg + OFF_B0 + off, sg + OFF_B1 + off, lb[p]);                        \
    } } while (0)

    float acc[2][8][4];
#pragma unroll
    for (int t = 0; t < 2; t++)
#pragma unroll
        for (int j = 0; j < 8; j++)
#pragma unroll
            for (int q = 0; q < 4; q++) acc[t][j][q] = 0.f;

    // per-lane ldmatrix row indices (fixed across chunks)
    const int rowA0 = wm * 32 + (lane & 7) + ((lane >> 3) & 1) * 8;   // + t*16
    const int kcA   = lane >> 4;
    const int rowB0 = wn * 64 + (lane & 7) + ((lane >> 4) & 1) * 8;   // + g*16
    const int kcB   = (lane >> 3) & 1;

    LOADC(0);
    STOREC(0);
    __syncthreads();

    for (int c = 0; c < NCHUNK; c++) {
        const int s = c & 1;
        if (c + 1 < NCHUNK) LOADC(c + 1);

        const uint32_t stb = sb + s * STAGE_BYTES;
#pragma unroll
        for (int kk = 0; kk < 2; kk++) {
            uint32_t af[2][2][4];
#pragma unroll
            for (int t = 0; t < 2; t++) {
                const int row = rowA0 + t * 16;
                const uint32_t base = stb + row * 64 +
                    ((((kk << 1) | kcA) ^ ((row >> 1) & 3)) << 4);
                LDSM4(af[t][0], base);
                LDSM4(af[t][1], base + OFF_A1);
            }
            uint32_t bfr[2][8][2];
#pragma unroll
            for (int g = 0; g < 4; g++) {
                const int row = rowB0 + g * 16;
                const uint32_t base = stb + OFF_B0 + row * 64 +
                    ((((kk << 1) | kcB) ^ ((row >> 1) & 3)) << 4);
                uint32_t q0[4], q1[4];
                LDSM4(q0, base);
                LDSM4(q1, base + 8192);   // B1 region
                bfr[0][2*g][0] = q0[0]; bfr[0][2*g][1] = q0[1];
                bfr[0][2*g+1][0] = q0[2]; bfr[0][2*g+1][1] = q0[3];
                bfr[1][2*g][0] = q1[0]; bfr[1][2*g][1] = q1[1];
                bfr[1][2*g+1][0] = q1[2]; bfr[1][2*g+1][1] = q1[3];
            }
#pragma unroll
            for (int t = 0; t < 2; t++)
#pragma unroll
                for (int j = 0; j < 8; j++) {
                    MMA16816(acc[t][j], af[t][0], bfr[0][j]);   // hi*hi
                    MMA16816(acc[t][j], af[t][0], bfr[1][j]);   // hi*lo
                    MMA16816(acc[t][j], af[t][1], bfr[0][j]);   // lo*hi
                }
        }

        if (c + 1 < NCHUNK) {
            STOREC(s ^ 1);
            __syncthreads();
        }
    }

    // epilogue: acc frag (t,j): c0,c1 -> row lane/4, cols (lane&3)*2; c2,c3 -> row+8
#pragma unroll
    for (int t = 0; t < 2; t++)
#pragma unroll
        for (int j = 0; j < 8; j++) {
            const int row = m0 + wm * 32 + t * 16 + (lane >> 2);
            const int col = n0 + wn * 64 + j * 8 + (lane & 3) * 2;
            const float cb0 = g_cbias[col], cb1 = g_cbias[col + 1];
            float2 v0 = make_float2(acc[t][j][0] + cb0, acc[t][j][1] + cb1);
            float2 v1 = make_float2(acc[t][j][2] + cb0, acc[t][j][3] + cb1);
            *(float2*)&g_pre[(size_t)row * F_DIM + col]       = v0;
            *(float2*)&g_pre[(size_t)(row + 8) * F_DIM + col] = v1;
        }
}

// ---------------- per-row top-64: radix select + fp64 boundary arbitration ----------------
__global__ __launch_bounds__(256) void topk_kernel(const float* __restrict__ x,
                                                   const float* __restrict__ W_enc,
                                                   const float* __restrict__ b_enc,
                                                   const float* __restrict__ b_dec) {
    extern __shared__ unsigned u[];            // 16384 keys (64KB)
    __shared__ unsigned whist[8][16];
    __shared__ unsigned tot[16];
    __shared__ unsigned sel[2];
    __shared__ unsigned gcnt[8];
    __shared__ unsigned gbase;
    __shared__ int s_ncand;
    __shared__ int      cand_idx[MAXCAND];
    __shared__ unsigned cand_key[MAXCAND];
    __shared__ double   cand_val[MAXCAND];
    __shared__ double   red[8];
    const int tid = threadIdx.x, wid = tid >> 5, lane = tid & 31;
    const int row = blockIdx.x;
    const float* __restrict__ src = g_pre + (size_t)row * F_DIM;

#pragma unroll
    for (int j = 0; j < 64; j++)
        u[tid + j * 256] = f2u(src[tid + j * 256]);

    unsigned prefix = 0;
    int need = TOPK;
    for (int shift = 28; shift >= 0; shift -= 4) {
        if (tid < 128) ((unsigned*)whist)[tid] = 0;
        __syncthreads();
        const unsigned maskhi = (shift == 28) ? 0u : (0xFFFFFFFFu << (shift + 4));
        for (int j = 0; j < 64; j++) {
            unsigned v = u[tid + j * 256];
            if ((v & maskhi) == prefix)
                atomicAdd(&whist[wid][(v >> shift) & 15u], 1u);
        }
        __syncthreads();
        if (tid < 16) {
            unsigned s = 0;
#pragma unroll
            for (int w = 0; w < 8; w++) s += whist[w][tid];
            tot[tid] = s;
        }
        __syncthreads();
        if (tid == 0) {
            int nd = need, b = 15;
            for (; b > 0; b--) {
                if ((int)tot[b] >= nd) break;
                nd -= (int)tot[b];
            }
            sel[0] = (unsigned)b;
            sel[1] = (unsigned)nd;
        }
        __syncthreads();
        prefix |= sel[0] << shift;
        need = (int)sel[1];
        __syncthreads();
    }

    const float vC = u2f(prefix);
    const unsigned keyHi = f2u(vC + EPS_WIN);
    const unsigned keyLo = f2u(vC - EPS_WIN);

    if (tid == 0) { gbase = 0; s_ncand = 0; }
    __syncthreads();

    float* vout = g_vals + (size_t)row * TOPK;
    int*   iout = g_idx + (size_t)row * TOPK;
    const unsigned lt = (1u << lane) - 1u;

    for (int base = 0; base < F_DIM; base += 256) {
        unsigned v = u[base + tid];
        bool fgt   = (v > keyHi);
        bool fcand = (v >= keyLo) && (v <= keyHi);
        unsigned balg = __ballot_sync(0xFFFFFFFFu, fgt);
        if (lane == 0) gcnt[wid] = __popc(balg);
        __syncthreads();
        if (tid == 0) {
            unsigned rg = gbase;
#pragma unroll
            for (int w = 0; w < 8; w++) {
                unsigned cg = gcnt[w]; gcnt[w] = rg; rg += cg;
            }
            gbase = rg;
        }
        __syncthreads();
        if (fgt) {
            int slot = (int)gcnt[wid] + __popc(balg & lt);
            iout[slot] = base + tid;
            vout[slot] = u2f(v);
        }
        if (fcand) {
            int p = atomicAdd(&s_ncand, 1);
            if (p < MAXCAND) { cand_idx[p] = base + tid; cand_key[p] = v; }
        }
        __syncthreads();
    }

    const int ncert = (int)gbase;
    const int slots = TOPK - ncert;
    int ncand = s_ncand;
    if (ncand > MAXCAND) ncand = MAXCAND;

    if (ncand > slots) {
        const float* __restrict__ xr = x + (size_t)row * D_DIM;
        for (int c = 0; c < ncand; c++) {
            const float* __restrict__ w = W_enc + (size_t)cand_idx[c] * D_DIM;
            double p = 0.0;
            for (int d = tid; d < D_DIM; d += 256)
                p += (double)(xr[d] - b_dec[d]) * (double)w[d];
#pragma unroll
            for (int o = 16; o > 0; o >>= 1) p += __shfl_xor_sync(0xFFFFFFFFu, p, o);
            if (lane == 0) red[wid] = p;
            __syncthreads();
            if (tid == 0) {
                double s = 0.0;
#pragma unroll
                for (int w8 = 0; w8 < 8; w8++) s += red[w8];
                cand_val[c] = s + (double)b_enc[cand_idx[c]];
            }
            __syncthreads();
        }
    }

    if (tid == 0) {
        bool used[MAXCAND];
        for (int c = 0; c < ncand; c++) used[c] = false;
        if (ncand == slots) {
            for (int s = 0; s < slots; s++) {
                int best = -1;
                for (int c = 0; c < ncand; c++)
                    if (!used[c] && (best < 0 || cand_idx[c] < cand_idx[best])) best = c;
                used[best] = true;
                iout[ncert + s] = cand_idx[best];
                vout[ncert + s] = u2f(cand_key[best]);
            }
        } else {
            for (int s = 0; s < slots; s++) {
                int best = -1;
                for (int c = 0; c < ncand; c++) {
                    if (used[c]) continue;
                    if (best < 0) { best = c; continue; }
                    bool b;
                    if (cand_key[c] == cand_key[best])      b = cand_idx[c] < cand_idx[best];
                    else if (cand_val[c] != cand_val[best]) b = cand_val[c] > cand_val[best];
                    else                                    b = cand_key[c] > cand_key[best];
                    if (b) best = c;
                }
                used[best] = true;
                iout[ncert + s] = cand_idx[best];
                vout[ncert + s] = u2f(cand_key[best]);
            }
        }
    }
}

// ---------------- sparse decode: out[b,:] = b_dec + sum_k val*W_decT[idx,:] ----------------
__global__ __launch_bounds__(256) void decode_kernel(const float* __restrict__ b_dec,
                                                     float* __restrict__ out) {
    __shared__ float sv[TOPK];
    __shared__ int   si[TOPK];
    const int row = blockIdx.x, tid = threadIdx.x;
    if (tid < TOPK) {
        sv[tid] = g_vals[(size_t)row * TOPK + tid];
        si[tid] = g_idx[(size_t)row * TOPK + tid];
    }
    __syncthreads();
    const float4* bd = (const float4*)b_dec;
    float4 a0 = bd[tid], a1 = bd[tid + 256];
#pragma unroll 4
    for (int k = 0; k < TOPK; k++) {
        const float v = sv[k];
        const float4* wr = (const float4*)(g_WdT + (size_t)si[k] * D_DIM);
        float4 w0 = wr[tid], w1 = wr[tid + 256];
        a0.x = fmaf(v, w0.x, a0.x); a0.y = fmaf(v, w0.y, a0.y);
        a0.z = fmaf(v, w0.z, a0.z); a0.w = fmaf(v, w0.w, a0.w);
        a1.x = fmaf(v, w1.x, a1.x); a1.y = fmaf(v, w1.y, a1.y);
        a1.z = fmaf(v, w1.z, a1.z); a1.w = fmaf(v, w1.w, a1.w);
    }
    float4* o = (float4*)out;
    o[(size_t)row * 512 + tid]       = a0;
    o[(size_t)row * 512 + 256 + tid] = a1;
}

// ---------------- launch ----------------
extern "C" void kernel_launch(void* const* d_in, const int* in_sizes, int n_in,
                              void* d_out, int out_size) {
    const float* x     = (const float*)d_in[0];
    const float* W_enc = (const float*)d_in[1];
    const float* b_enc = (const float*)d_in[2];
    const float* W_dec = (const float*)d_in[3];
    const float* b_dec = (const float*)d_in[4];
    float* out = (float*)d_out;

    cbias_kernel<<<F_DIM / 8, 256>>>(W_enc, b_enc, b_dec);
    transpose_kernel<<<dim3(F_DIM / 32, D_DIM / 32), dim3(32, 8)>>>(W_dec);

    cudaFuncSetAttribute(gemm_mma_kernel, cudaFuncAttributeMaxDynamicSharedMemorySize, SMEM_GEMM);
    gemm_mma_kernel<<<NT_M * NT_N, 256, SMEM_GEMM>>>(x, W_enc);

    cudaFuncSetAttribute(topk_kernel, cudaFuncAttributeMaxDynamicSharedMemorySize, 65536);
    topk_kernel<<<B_TOK, 256, 65536>>>(x, W_enc, b_enc, b_dec);
    decode_kernel<<<B_TOK, 256>>>(b_dec, out);
}

// round 12
// speedup vs baseline: 2.1921x; 1.0976x over previous
#include <cuda_runtime.h>
#include <cuda_bf16.h>
#include <cstdint>

#define B_TOK 8192
#define D_DIM 2048
#define F_DIM 16384
#define TOPK  64
#define EPS_WIN 6e-4f
#define MAXCAND 128

// ---- GEMM tiling ----
#define TM 128
#define TN 128
#define KT 32
#define NCHUNK (D_DIM / KT)      // 64
#define NT_M (B_TOK / TM)        // 64
#define NT_N (F_DIM / TN)        // 128
// per-stage smem: Ahi(8K) Alo(8K) Bhi(8K) Blo(8K) = 32KB; 4 stages = 128KB
#define STAGE_BYTES 32768
#define R_ALO 8192
#define R_BHI 16384
#define R_BLO 24576
#define NSTAGE 4
#define SMEM_GEMM (NSTAGE * STAGE_BYTES)

// ---------------- scratch (static device globals; no allocation) ----------------
__device__ __align__(256) float g_pre[(size_t)B_TOK * F_DIM];   // 512 MB
__device__ __align__(256) float g_WdT[(size_t)F_DIM * D_DIM];   // 128 MB
__device__ __align__(256) float g_cbias[F_DIM];
__device__ __align__(256) float g_vals[B_TOK * TOPK];
__device__ __align__(256) int   g_idx[B_TOK * TOPK];
// pre-split bf16 operands (hi/lo)
__device__ __align__(256) __nv_bfloat16 g_Ahi[(size_t)B_TOK * D_DIM];   // 32 MB
__device__ __align__(256) __nv_bfloat16 g_Alo[(size_t)B_TOK * D_DIM];   // 32 MB
__device__ __align__(256) __nv_bfloat16 g_Whi[(size_t)F_DIM * D_DIM];   // 64 MB
__device__ __align__(256) __nv_bfloat16 g_Wlo[(size_t)F_DIM * D_DIM];   // 64 MB

// ---------------- helpers ----------------
__device__ __forceinline__ uint32_t smem_u32(const void* p) {
    uint32_t a;
    asm("{ .reg .u64 t; cvta.to.shared.u64 t, %1; cvt.u32.u64 %0, t; }" : "=r"(a) : "l"(p));
    return a;
}
#define CP16(dst, src) \
    asm volatile("cp.async.ca.shared.global [%0], [%1], 16;" :: "r"(dst), "l"(src) : "memory")
#define CP_COMMIT() asm volatile("cp.async.commit_group;" ::: "memory")
#define CP_WAIT2()  asm volatile("cp.async.wait_group 2;" ::: "memory")
#define LDSM4(r, a) \
    asm volatile("ldmatrix.sync.aligned.m8n8.x4.shared.b16 {%0,%1,%2,%3}, [%4];" \
        : "=r"((r)[0]), "=r"((r)[1]), "=r"((r)[2]), "=r"((r)[3]) : "r"(a))
#define MMA16816(c, a, b) \
    asm volatile("mma.sync.aligned.m16n8k16.row.col.f32.bf16.bf16.f32 " \
        "{%0,%1,%2,%3}, {%4,%5,%6,%7}, {%8,%9}, {%0,%1,%2,%3};" \
        : "+f"((c)[0]), "+f"((c)[1]), "+f"((c)[2]), "+f"((c)[3]) \
        : "r"((a)[0]), "r"((a)[1]), "r"((a)[2]), "r"((a)[3]), "r"((b)[0]), "r"((b)[1]))

__device__ __forceinline__ uint32_t bfpack(__nv_bfloat16 a, __nv_bfloat16 b) {
    return (uint32_t)__bfloat16_as_ushort(a) | ((uint32_t)__bfloat16_as_ushort(b) << 16);
}
// monotone float<->uint mapping for radix select
__device__ __forceinline__ unsigned f2u(float f) {
    unsigned v = __float_as_uint(f);
    return (v & 0x80000000u) ? ~v : (v | 0x80000000u);
}
__device__ __forceinline__ float u2f(unsigned v) {
    unsigned o = (v & 0x80000000u) ? (v ^ 0x80000000u) : ~v;
    return __uint_as_float(o);
}

// ---------------- split fp32 -> bf16 hi/lo (globals referenced directly) ----------------
// mode 0: x -> g_Ahi/g_Alo ; mode 1: W_enc -> g_Whi/g_Wlo
__global__ void split_kernel(const float* __restrict__ src, int n4, int mode) {
    int i = blockIdx.x * blockDim.x + threadIdx.x;
    if (i >= n4) return;
    __nv_bfloat16* hi = mode ? g_Whi : g_Ahi;
    __nv_bfloat16* lo = mode ? g_Wlo : g_Alo;
    float4 v = ((const float4*)src)[i];
    __nv_bfloat16 hx = __float2bfloat16_rn(v.x), hy = __float2bfloat16_rn(v.y);
    __nv_bfloat16 hz = __float2bfloat16_rn(v.z), hw = __float2bfloat16_rn(v.w);
    __nv_bfloat16 lx = __float2bfloat16_rn(v.x - __bfloat162float(hx));
    __nv_bfloat16 ly = __float2bfloat16_rn(v.y - __bfloat162float(hy));
    __nv_bfloat16 lz = __float2bfloat16_rn(v.z - __bfloat162float(hz));
    __nv_bfloat16 lw = __float2bfloat16_rn(v.w - __bfloat162float(hw));
    ((uint2*)hi)[i] = make_uint2(bfpack(hx, hy), bfpack(hz, hw));
    ((uint2*)lo)[i] = make_uint2(bfpack(lx, ly), bfpack(lz, lw));
}

// ---------------- cbias[f] = b_enc[f] - dot(b_dec, W_enc[f,:]) ----------------
__global__ void cbias_kernel(const float* __restrict__ W_enc,
                             const float* __restrict__ b_enc,
                             const float* __restrict__ b_dec) {
    int wid  = threadIdx.x >> 5;
    int lane = threadIdx.x & 31;
    int f    = blockIdx.x * 8 + wid;
    const float* w = W_enc + (size_t)f * D_DIM;
    float s = 0.f;
    for (int d = lane; d < D_DIM; d += 32) s += b_dec[d] * w[d];
#pragma unroll
    for (int o = 16; o > 0; o >>= 1) s += __shfl_xor_sync(0xFFFFFFFFu, s, o);
    if (lane == 0) g_cbias[f] = b_enc[f] - s;
}

// ---------------- W_decT[f][d] = W_dec[d][f] ----------------
__global__ void transpose_kernel(const float* __restrict__ W_dec) {
    __shared__ float t[32][33];
    int fb = blockIdx.x * 32, db = blockIdx.y * 32;
    int tx = threadIdx.x, ty = threadIdx.y;  // 32 x 8
#pragma unroll
    for (int i = 0; i < 32; i += 8)
        t[ty + i][tx] = W_dec[(size_t)(db + ty + i) * F_DIM + fb + tx];
    __syncthreads();
#pragma unroll
    for (int i = 0; i < 32; i += 8)
        g_WdT[(size_t)(fb + ty + i) * D_DIM + db + tx] = t[tx][ty + i];
}

// ---------------- encode GEMM: cp.async 4-stage pipeline, bf16 3-product mma ----------------
// CTA tile 128x128, K chunk 32, 8 warps in 4(M) x 2(N), warp tile 32x64.
__global__ __launch_bounds__(256, 1) void gemm_mma_kernel() {
    extern __shared__ char smem[];
    const uint32_t sb = smem_u32(smem);
    const int tid = threadIdx.x, lane = tid & 31, wid = tid >> 5;
    const int wm = wid & 3, wn = wid >> 2;

    // grid swizzle: groups of 8 N-tiles over all 64 M-tiles
    const int group = blockIdx.x >> 9;
    const int rr    = blockIdx.x & 511;
    const int nt    = group * 8 + (rr & 7);
    const int mt    = rr >> 3;
    const int m0 = mt * TM, n0 = nt * TN;

    // ---- cp.async loader mapping: thread -> (row, 16B chunk); 2 rows per region ----
    const int lrow = tid >> 2;            // 0..63
    const int lch  = tid & 3;             // 16B chunk within 64B row
    const uint32_t off0 = (uint32_t)lrow * 64u + (uint32_t)((lch ^ ((lrow >> 1) & 3)) << 4);
    // row+64 has identical swizzle (64 is 0 mod 4 after >>1)
    const __nv_bfloat16* pAhi = g_Ahi + (size_t)(m0 + lrow) * D_DIM + lch * 8;
    const __nv_bfloat16* pAlo = g_Alo + (size_t)(m0 + lrow) * D_DIM + lch * 8;
    const __nv_bfloat16* pBhi = g_Whi + (size_t)(n0 + lrow) * D_DIM + lch * 8;
    const __nv_bfloat16* pBlo = g_Wlo + (size_t)(n0 + lrow) * D_DIM + lch * 8;
    const size_t rstep = (size_t)64 * D_DIM;

#define ISSUE(cc) do {                                                         \
    const uint32_t _b = sb + ((cc) & 3) * STAGE_BYTES;                         \
    const int _k = (cc) * KT;                                                  \
    CP16(_b + off0,                 pAhi + _k);                                \
    CP16(_b + off0 + 4096,          pAhi + rstep + _k);                        \
    CP16(_b + R_ALO + off0,         pAlo + _k);                                \
    CP16(_b + R_ALO + off0 + 4096,  pAlo + rstep + _k);                        \
    CP16(_b + R_BHI + off0,         pBhi + _k);                                \
    CP16(_b + R_BHI + off0 + 4096,  pBhi + rstep + _k);                        \
    CP16(_b + R_BLO + off0,         pBlo + _k);                                \
    CP16(_b + R_BLO + off0 + 4096,  pBlo + rstep + _k);                        \
    CP_COMMIT();                                                               \
} while (0)

    float acc[2][8][4];
#pragma unroll
    for (int t = 0; t < 2; t++)
#pragma unroll
        for (int j = 0; j < 8; j++)
#pragma unroll
            for (int q = 0; q < 4; q++) acc[t][j][q] = 0.f;

    // per-lane ldmatrix row indices (fixed across chunks)
    const int rowA0 = wm * 32 + (lane & 7) + ((lane >> 3) & 1) * 8;   // + t*16
    const int kcA   = lane >> 4;
    const int rowB0 = wn * 64 + (lane & 7) + ((lane >> 4) & 1) * 8;   // + g*16
    const int kcB   = (lane >> 3) & 1;

    ISSUE(0); ISSUE(1); ISSUE(2);

    for (int c = 0; c < NCHUNK; c++) {
        CP_WAIT2();
        __syncthreads();

        const uint32_t stb = sb + (c & 3) * STAGE_BYTES;
#pragma unroll
        for (int kk = 0; kk < 2; kk++) {
            uint32_t af[2][2][4];
#pragma unroll
            for (int t = 0; t < 2; t++) {
                const int row = rowA0 + t * 16;
                const uint32_t base = stb + row * 64 +
                    ((((kk << 1) | kcA) ^ ((row >> 1) & 3)) << 4);
                LDSM4(af[t][0], base);
                LDSM4(af[t][1], base + R_ALO);
            }
            uint32_t bfr[2][8][2];
#pragma unroll
            for (int g = 0; g < 4; g++) {
                const int row = rowB0 + g * 16;
                const uint32_t base = stb + R_BHI + row * 64 +
                    ((((kk << 1) | kcB) ^ ((row >> 1) & 3)) << 4);
                uint32_t q0[4], q1[4];
                LDSM4(q0, base);
                LDSM4(q1, base + 8192);   // Blo region
                bfr[0][2*g][0] = q0[0]; bfr[0][2*g][1] = q0[1];
                bfr[0][2*g+1][0] = q0[2]; bfr[0][2*g+1][1] = q0[3];
                bfr[1][2*g][0] = q1[0]; bfr[1][2*g][1] = q1[1];
                bfr[1][2*g+1][0] = q1[2]; bfr[1][2*g+1][1] = q1[3];
            }
            // product-outer ordering: same-acc reuse distance = 16 MMAs
#pragma unroll
            for (int t = 0; t < 2; t++)
#pragma unroll
                for (int j = 0; j < 8; j++)
                    MMA16816(acc[t][j], af[t][0], bfr[0][j]);   // hi*hi
#pragma unroll
            for (int t = 0; t < 2; t++)
#pragma unroll
                for (int j = 0; j < 8; j++)
                    MMA16816(acc[t][j], af[t][0], bfr[1][j]);   // hi*lo
#pragma unroll
            for (int t = 0; t < 2; t++)
#pragma unroll
                for (int j = 0; j < 8; j++)
                    MMA16816(acc[t][j], af[t][1], bfr[0][j]);   // lo*hi
        }

        __syncthreads();
        if (c + 3 < NCHUNK) ISSUE(c + 3);
    }

    // epilogue: acc frag (t,j): c0,c1 -> row lane/4, cols (lane&3)*2; c2,c3 -> row+8
#pragma unroll
    for (int t = 0; t < 2; t++)
#pragma unroll
        for (int j = 0; j < 8; j++) {
            const int row = m0 + wm * 32 + t * 16 + (lane >> 2);
            const int col = n0 + wn * 64 + j * 8 + (lane & 3) * 2;
            const float cb0 = g_cbias[col], cb1 = g_cbias[col + 1];
            float2 v0 = make_float2(acc[t][j][0] + cb0, acc[t][j][1] + cb1);
            float2 v1 = make_float2(acc[t][j][2] + cb0, acc[t][j][3] + cb1);
            *(float2*)&g_pre[(size_t)row * F_DIM + col]       = v0;
            *(float2*)&g_pre[(size_t)(row + 8) * F_DIM + col] = v1;
        }
}

// ---------------- per-row top-64: radix select + fp64 boundary arbitration ----------------
__global__ __launch_bounds__(256) void topk_kernel(const float* __restrict__ x,
                                                   const float* __restrict__ W_enc,
                                                   const float* __restrict__ b_enc,
                                                   const float* __restrict__ b_dec) {
    extern __shared__ unsigned u[];            // 16384 keys (64KB)
    __shared__ unsigned whist[8][16];
    __shared__ unsigned tot[16];
    __shared__ unsigned sel[2];
    __shared__ unsigned gcnt[8];
    __shared__ unsigned gbase;
    __shared__ int s_ncand;
    __shared__ int      cand_idx[MAXCAND];
    __shared__ unsigned cand_key[MAXCAND];
    __shared__ double   cand_val[MAXCAND];
    __shared__ double   red[8];
    const int tid = threadIdx.x, wid = tid >> 5, lane = tid & 31;
    const int row = blockIdx.x;
    const float* __restrict__ src = g_pre + (size_t)row * F_DIM;

#pragma unroll
    for (int j = 0; j < 64; j++)
        u[tid + j * 256] = f2u(src[tid + j * 256]);

    unsigned prefix = 0;
    int need = TOPK;
    for (int shift = 28; shift >= 0; shift -= 4) {
        if (tid < 128) ((unsigned*)whist)[tid] = 0;
        __syncthreads();
        const unsigned maskhi = (shift == 28) ? 0u : (0xFFFFFFFFu << (shift + 4));
        for (int j = 0; j < 64; j++) {
            unsigned v = u[tid + j * 256];
            if ((v & maskhi) == prefix)
                atomicAdd(&whist[wid][(v >> shift) & 15u], 1u);
        }
        __syncthreads();
        if (tid < 16) {
            unsigned s = 0;
#pragma unroll
            for (int w = 0; w < 8; w++) s += whist[w][tid];
            tot[tid] = s;
        }
        __syncthreads();
        if (tid == 0) {
            int nd = need, b = 15;
            for (; b > 0; b--) {
                if ((int)tot[b] >= nd) break;
                nd -= (int)tot[b];
            }
            sel[0] = (unsigned)b;
            sel[1] = (unsigned)nd;
        }
        __syncthreads();
        prefix |= sel[0] << shift;
        need = (int)sel[1];
        __syncthreads();
    }

    const float vC = u2f(prefix);
    const unsigned keyHi = f2u(vC + EPS_WIN);
    const unsigned keyLo = f2u(vC - EPS_WIN);

    if (tid == 0) { gbase = 0; s_ncand = 0; }
    __syncthreads();

    float* vout = g_vals + (size_t)row * TOPK;
    int*   iout = g_idx + (size_t)row * TOPK;
    const unsigned lt = (1u << lane) - 1u;

    for (int base = 0; base < F_DIM; base += 256) {
        unsigned v = u[base + tid];
        bool fgt   = (v > keyHi);
        bool fcand = (v >= keyLo) && (v <= keyHi);
        unsigned balg = __ballot_sync(0xFFFFFFFFu, fgt);
        if (lane == 0) gcnt[wid] = __popc(balg);
        __syncthreads();
        if (tid == 0) {
            unsigned rg = gbase;
#pragma unroll
            for (int w = 0; w < 8; w++) {
                unsigned cg = gcnt[w]; gcnt[w] = rg; rg += cg;
            }
            gbase = rg;
        }
        __syncthreads();
        if (fgt) {
            int slot = (int)gcnt[wid] + __popc(balg & lt);
            iout[slot] = base + tid;
            vout[slot] = u2f(v);
        }
        if (fcand) {
            int p = atomicAdd(&s_ncand, 1);
            if (p < MAXCAND) { cand_idx[p] = base + tid; cand_key[p] = v; }
        }
        __syncthreads();
    }

    const int ncert = (int)gbase;
    const int slots = TOPK - ncert;
    int ncand = s_ncand;
    if (ncand > MAXCAND) ncand = MAXCAND;

    if (ncand > slots) {
        const float* __restrict__ xr = x + (size_t)row * D_DIM;
        for (int c = 0; c < ncand; c++) {
            const float* __restrict__ w = W_enc + (size_t)cand_idx[c] * D_DIM;
            double p = 0.0;
            for (int d = tid; d < D_DIM; d += 256)
                p += (double)(xr[d] - b_dec[d]) * (double)w[d];
#pragma unroll
            for (int o = 16; o > 0; o >>= 1) p += __shfl_xor_sync(0xFFFFFFFFu, p, o);
            if (lane == 0) red[wid] = p;
            __syncthreads();
            if (tid == 0) {
                double s = 0.0;
#pragma unroll
                for (int w8 = 0; w8 < 8; w8++) s += red[w8];
                cand_val[c] = s + (double)b_enc[cand_idx[c]];
            }
            __syncthreads();
        }
    }

    if (tid == 0) {
        bool used[MAXCAND];
        for (int c = 0; c < ncand; c++) used[c] = false;
        if (ncand == slots) {
            for (int s = 0; s < slots; s++) {
                int best = -1;
                for (int c = 0; c < ncand; c++)
                    if (!used[c] && (best < 0 || cand_idx[c] < cand_idx[best])) best = c;
                used[best] = true;
                iout[ncert + s] = cand_idx[best];
                vout[ncert + s] = u2f(cand_key[best]);
            }
        } else {
            for (int s = 0; s < slots; s++) {
                int best = -1;
                for (int c = 0; c < ncand; c++) {
                    if (used[c]) continue;
                    if (best < 0) { best = c; continue; }
                    bool b;
                    if (cand_key[c] == cand_key[best])      b = cand_idx[c] < cand_idx[best];
                    else if (cand_val[c] != cand_val[best]) b = cand_val[c] > cand_val[best];
                    else                                    b = cand_key[c] > cand_key[best];
                    if (b) best = c;
                }
                used[best] = true;
                iout[ncert + s] = cand_idx[best];
                vout[ncert + s] = u2f(cand_key[best]);
            }
        }
    }
}

// ---------------- sparse decode: out[b,:] = b_dec + sum_k val*W_decT[idx,:] ----------------
__global__ __launch_bounds__(256) void decode_kernel(const float* __restrict__ b_dec,
                                                     float* __restrict__ out) {
    __shared__ float sv[TOPK];
    __shared__ int   si[TOPK];
    const int row = blockIdx.x, tid = threadIdx.x;
    if (tid < TOPK) {
        sv[tid] = g_vals[(size_t)row * TOPK + tid];
        si[tid] = g_idx[(size_t)row * TOPK + tid];
    }
    __syncthreads();
    const float4* bd = (const float4*)b_dec;
    float4 a0 = bd[tid], a1 = bd[tid + 256];
#pragma unroll 8
    for (int k = 0; k < TOPK; k++) {
        const float v = sv[k];
        const float4* wr = (const float4*)(g_WdT + (size_t)si[k] * D_DIM);
        float4 w0 = __ldg(wr + tid), w1 = __ldg(wr + tid + 256);
        a0.x = fmaf(v, w0.x, a0.x); a0.y = fmaf(v, w0.y, a0.y);
        a0.z = fmaf(v, w0.z, a0.z); a0.w = fmaf(v, w0.w, a0.w);
        a1.x = fmaf(v, w1.x, a1.x); a1.y = fmaf(v, w1.y, a1.y);
        a1.z = fmaf(v, w1.z, a1.z); a1.w = fmaf(v, w1.w, a1.w);
    }
    float4* o = (float4*)out;
    o[(size_t)row * 512 + tid]       = a0;
    o[(size_t)row * 512 + 256 + tid] = a1;
}

// ---------------- launch ----------------
extern "C" void kernel_launch(void* const* d_in, const int* in_sizes, int n_in,
                              void* d_out, int out_size) {
    const float* x     = (const float*)d_in[0];
    const float* W_enc = (const float*)d_in[1];
    const float* b_enc = (const float*)d_in[2];
    const float* W_dec = (const float*)d_in[3];
    const float* b_dec = (const float*)d_in[4];
    float* out = (float*)d_out;

    split_kernel<<<(B_TOK * D_DIM / 4 + 255) / 256, 256>>>(x, B_TOK * D_DIM / 4, 0);
    split_kernel<<<(F_DIM * D_DIM / 4 + 255) / 256, 256>>>(W_enc, F_DIM * D_DIM / 4, 1);
    cbias_kernel<<<F_DIM / 8, 256>>>(W_enc, b_enc, b_dec);
    transpose_kernel<<<dim3(F_DIM / 32, D_DIM / 32), dim3(32, 8)>>>(W_dec);

    cudaFuncSetAttribute(gemm_mma_kernel, cudaFuncAttributeMaxDynamicSharedMemorySize, SMEM_GEMM);
    gemm_mma_kernel<<<NT_M * NT_N, 256, SMEM_GEMM>>>();

    cudaFuncSetAttribute(topk_kernel, cudaFuncAttributeMaxDynamicSharedMemorySize, 65536);
    topk_kernel<<<B_TOK, 256, 65536>>>(x, W_enc, b_enc, b_dec);
    decode_kernel<<<B_TOK, 256>>>(b_dec, out);
}